// round 10
// baseline (speedup 1.0000x reference)
#include <cuda_runtime.h>
#include <cuda_fp16.h>
#include <math.h>
#include <stdint.h>

// ---------------------------------------------------------------------------
// EquiConv v9: fp16 HMMA, TILE_R=32, grid 2048 (wave tail ~1%), XOR-swizzled
//              B smem (16KB/chunk), triple buffer, ONE sync per chunk,
//              hoisted A fragments, warps = (rg 0..1) x (cg 0..3), occ=2.
// ---------------------------------------------------------------------------

#define E_ROWS 65536
#define TILE_R 32
#define NCHUNK 18
#define A_BYTES (TILE_R*64*2)       // 4096, swizzled rows of 128B
#define BS_OFF  A_BYTES
#define BBUF_B  (128*64*2)          // 16384 (one chunk, swizzled, no pad)
#define SMEM_TOTAL (A_BYTES + 3*BBUF_B)   // 53248

__device__ float g_H[E_ROWS * 64];
__device__ float g_C[E_ROWS * 48];
__device__ __align__(16) __half g_B[NCHUNK * 128 * 64];

// ------------------------------ asm helpers --------------------------------
__device__ __forceinline__ uint32_t smem_u32(const void* p) {
    uint32_t a;
    asm("{ .reg .u64 t; cvta.to.shared.u64 t, %1; cvt.u32.u64 %0, t; }" : "=r"(a) : "l"(p));
    return a;
}
#define LDSM4(r, a)                                                          \
    asm volatile("ldmatrix.sync.aligned.m8n8.x4.shared.b16 {%0,%1,%2,%3},[%4];" \
                 : "=r"((r)[0]), "=r"((r)[1]), "=r"((r)[2]), "=r"((r)[3]) : "r"(a))
#define MMA16816(d, a, b0, b1)                                               \
    asm volatile("mma.sync.aligned.m16n8k16.row.col.f32.f16.f16.f32 "        \
                 "{%0,%1,%2,%3},{%4,%5,%6,%7},{%8,%9},{%0,%1,%2,%3};"        \
                 : "+f"((d)[0]), "+f"((d)[1]), "+f"((d)[2]), "+f"((d)[3])    \
                 : "r"((a)[0]), "r"((a)[1]), "r"((a)[2]), "r"((a)[3]),       \
                   "r"(b0), "r"(b1))
#define CP_ASYNC16(d, s) \
    asm volatile("cp.async.cg.shared.global [%0], [%1], 16;" :: "r"(d), "l"(s))
#define CP_COMMIT()   asm volatile("cp.async.commit_group;" ::: "memory")
#define CP_WAIT1()    asm volatile("cp.async.wait_group 1;" ::: "memory")
#define CP_WAIT0()    asm volatile("cp.async.wait_group 0;" ::: "memory")

// swizzled byte offset inside a [rows x 64fp16] tile: row*128 + (unit^(row&7))*16
__device__ __forceinline__ uint32_t swz(int row, int unit) {
    return (uint32_t)(row * 128 + ((unit ^ (row & 7)) << 4));
}

// stage one chunk (128 rows x 128B) into swizzled smem
__device__ __forceinline__ void stage_B(int chunk, uint32_t dst, int tid) {
    const char* src = (const char*)(g_B + chunk * 128 * 64);
#pragma unroll
    for (int it = 0; it < 4; it++) {
        int t16 = tid + it * 256;
        int row = t16 >> 3, c = t16 & 7;
        CP_ASYNC16(dst + swz(row, c), src + t16 * 16);
    }
}

// ---------------------------------------------------------------------------
__global__ void k01_prep(const float* __restrict__ fea_in1,
                         const float* __restrict__ fea_in2,
                         const float* __restrict__ fea_weight,
                         const float* __restrict__ W1,
                         const float* __restrict__ W2)
{
    __shared__ float W1s[64 * 64];
    __shared__ float fws[32 * 64];
    const int t  = threadIdx.x;
    const int r0 = blockIdx.x * 32;

    // ---- k0 part: W2 -> g_B fp16, chunked layout (blocks < 576) ----
    if (blockIdx.x < 576) {
        int id = blockIdx.x * 256 + t;     // covers 2304*64 exactly
        int col = id >> 6, kk = id & 63;
        int chunk = col >> 7, n = col & 127;
        g_B[(chunk * 128 + n) * 64 + kk] = __float2half(W2[kk * 2304 + col]);
    }

    // ---- k1 part ----
    for (int idx = t; idx < 64 * 64; idx += 256) W1s[idx] = W1[idx];
    for (int idx = t; idx < 32 * 64; idx += 256) fws[idx] = fea_weight[r0 * 64 + idx];
    __syncthreads();

    const int rl = t >> 3, l8 = t & 7, grow = r0 + rl;
    float acc[8];
#pragma unroll
    for (int jj = 0; jj < 8; jj++) acc[jj] = 0.f;
#pragma unroll 8
    for (int k = 0; k < 64; k++) {
        const float fv = fws[rl * 64 + k];
#pragma unroll
        for (int jj = 0; jj < 8; jj++) acc[jj] += fv * W1s[k * 64 + jj * 8 + l8];
    }
#pragma unroll
    for (int jj = 0; jj < 8; jj++) {
        const float z = acc[jj] * 0.125f;
        const float s = z / (1.f + expf(-z));
        g_H[grow * 64 + jj * 8 + l8] = 1.679f * s * 0.125f;   // fold W2's /8
    }

    const float x20  = fea_in2[grow * 4 + 0];
    const float x21a = fea_in2[grow * 4 + 1];
    const float x21b = fea_in2[grow * 4 + 2];
    const float x21c = fea_in2[grow * 4 + 3];
    for (int u = l8; u < 32; u += 8)
        g_C[grow * 48 + u] = 0.125f * x20 * fea_in1[grow * 80 + u];      // pw00
    for (int u = l8; u < 16; u += 8) {
        const float* p = fea_in1 + grow * 80 + 32 + u * 3;
        const float b = p[0] * x21a + p[1] * x21b + p[2] * x21c;
        g_C[grow * 48 + 32 + u] = 0.10206207261596575f * b;              // 1/sqrt(96)
    }
}

// ---------------------------------------------------------------------------
__global__ __launch_bounds__(256, 2)
void k2_main(const float* __restrict__ fea_in1,
             const float* __restrict__ fea_in2,
             float* __restrict__ out)
{
    extern __shared__ __align__(16) char smem[];
    const uint32_t sbase = smem_u32(smem);
    const int tid = threadIdx.x, wid = tid >> 5, lane = tid & 31;
    const int rg = wid >> 2, cg = wid & 3;
    const int r0 = blockIdx.x * TILE_R;

    // ---- build A tile: [32 rows][64 k] fp16, swizzled 128B rows ----
    {
        __half* As = (__half*)smem;
        for (int idx = tid; idx < TILE_R * 64; idx += 256) {
            const int r = idx >> 6, j = idx & 63;
            const uint32_t off = swz(r, j >> 3) + (j & 7) * 2;
            *(__half*)((char*)As + off) = __float2half(g_H[(r0 + r) * 64 + j]);
        }
    }
    stage_B(0, sbase + BS_OFF, tid);              CP_COMMIT();
    stage_B(1, sbase + BS_OFF + BBUF_B, tid);     CP_COMMIT();
    __syncthreads();   // A tile visible for fragment hoist

    // ldmatrix geometry
    const int gp = lane >> 3, lr = lane & 7;

    // hoist A fragments: row = rg*16 + 8*(gp&1) + lr ; unit = (gp>>1) + 2*ksb
    uint32_t afrag[4][4];
    {
        const int arow = rg * 16 + 8 * (gp & 1) + lr;
#pragma unroll
        for (int ksb = 0; ksb < 4; ksb++)
            LDSM4(afrag[ksb], sbase + swz(arow, (gp >> 1) + 2 * ksb));
    }

    // B lane geometry: p in {0,1}: row = cg*32 + 16p + 8*(gp>>1) + lr
    const int brow0 = cg * 32 + 8 * (gp >> 1) + lr;
    const uint32_t bline0 = (uint32_t)(brow0 * 128),  brs0 = (uint32_t)(brow0 & 7);
    const uint32_t bline1 = (uint32_t)((brow0 + 16) * 128), brs1 = (uint32_t)((brow0 + 16) & 7);
    const uint32_t cb = (uint32_t)(gp & 1);

    // persistent per-thread partial accumulators
    float o0[16], sA[8], qA[24];
#pragma unroll
    for (int i = 0; i < 16; i++) o0[i] = 0.f;
#pragma unroll
    for (int i = 0; i < 8; i++) sA[i] = 0.f;
#pragma unroll
    for (int i = 0; i < 24; i++) qA[i] = 0.f;

    const int rowq = lane >> 2;
    const int rbase = r0 + rg * 16 + rowq;     // + rh*8
    const int q2 = (lane & 3) * 2;

#pragma unroll 1
    for (int m = 0; m < NCHUNK; m++) {
        if (m < NCHUNK - 1) { CP_WAIT1(); } else { CP_WAIT0(); }
        __syncthreads();
        if (m + 2 < NCHUNK) {   // buf[(m+2)%3]'s last reader was chunk m-1 (done)
            stage_B(m + 2, sbase + BS_OFF + (uint32_t)((m + 2) % 3) * BBUF_B, tid);
            CP_COMMIT();
        }
        const uint32_t sbB = sbase + BS_OFF + (uint32_t)(m % 3) * BBUF_B;

        float acc[4][4];
#pragma unroll
        for (int jj = 0; jj < 4; jj++)
#pragma unroll
            for (int c = 0; c < 4; c++) acc[jj][c] = 0.f;

#pragma unroll
        for (int ksb = 0; ksb < 4; ksb++) {
            const uint32_t cu = cb + 2 * ksb;
            uint32_t r[4], r2[4];
            LDSM4(r,  sbB + bline0 + (((cu ^ brs0)) << 4));
            LDSM4(r2, sbB + bline1 + (((cu ^ brs1)) << 4));
            MMA16816(acc[0], afrag[ksb], r[0],  r[1]);
            MMA16816(acc[1], afrag[ksb], r[2],  r[3]);
            MMA16816(acc[2], afrag[ksb], r2[0], r2[1]);
            MMA16816(acc[3], afrag[ksb], r2[2], r2[3]);
        }

        // ---- fragment-local contraction (cg-partial) ----
        // warp cols within chunk: cg*32 + j*8 + q2 + {0,1}, j=0..3
        if (m < 12) {
            // seg0/1: single u per warp-chunk: u = m*4+cg (m<8) | 32+(m-8)*4+cg
            const int ubase = (m < 8 ? m * 4 : 32 + (m - 8) * 4) + cg;
#pragma unroll
            for (int rh = 0; rh < 2; rh++) {
                const int row = rbase + rh * 8;
                const float c = g_C[row * 48 + ubase];
#pragma unroll
                for (int j = 0; j < 4; j++) {
                    const int s = (rh * 4 + j) * 2;
                    o0[s]     = fmaf(c, acc[j][rh * 2],     o0[s]);
                    o0[s + 1] = fmaf(c, acc[j][rh * 2 + 1], o0[s + 1]);
                }
            }
        } else if (m < 16) {
            // seg2: u = (m-12)*8 + cg*2 + (j>>1); w = (j&1)*8 + q2 + {0,1}
            const int u0 = (m - 12) * 8 + cg * 2;
#pragma unroll
            for (int rh = 0; rh < 2; rh++) {
                const int row = rbase + rh * 8;
                const float* xr = fea_in1 + row * 80 + u0;
#pragma unroll
                for (int j = 0; j < 4; j++) {
                    const float cu = xr[j >> 1];
                    const int s = rh * 4 + (j & 1) * 2;
                    sA[s]     = fmaf(cu, acc[j][rh * 2],     sA[s]);
                    sA[s + 1] = fmaf(cu, acc[j][rh * 2 + 1], sA[s + 1]);
                }
            }
        } else {
            // seg3: u = (m-16)*8 + cg*2 + (j>>1); coef = x1_1[u, 0..2]
            const int u0 = (m - 16) * 8 + cg * 2;
#pragma unroll
            for (int rh = 0; rh < 2; rh++) {
                const int row = rbase + rh * 8;
                const float* xr = fea_in1 + row * 80 + 32 + 3 * u0;
#pragma unroll
                for (int j = 0; j < 4; j++) {
                    const int s = (rh * 4 + (j & 1) * 2) * 3;
#pragma unroll
                    for (int k = 0; k < 3; k++) {
                        const float cu = xr[3 * (j >> 1) + k];
                        qA[s + k]     = fmaf(cu, acc[j][rh * 2],     qA[s + k]);
                        qA[s + 3 + k] = fmaf(cu, acc[j][rh * 2 + 1], qA[s + 3 + k]);
                    }
                }
            }
        }
    }

    // ---- cross-cg reduction (cg=1..3 partials -> cg=0), reuse B area ----
    __syncthreads();
    float* red = (float*)(smem + BS_OFF);      // 3 * 64 thr * 48 f = 36864 B
    const int half_id = rg * 32 + lane;        // 0..63
    if (cg != 0) {
        float* dst = red + ((cg - 1) * 64 + half_id) * 48;
#pragma unroll
        for (int i = 0; i < 16; i++) dst[i] = o0[i];
#pragma unroll
        for (int i = 0; i < 8; i++) dst[16 + i] = sA[i];
#pragma unroll
        for (int i = 0; i < 24; i++) dst[24 + i] = qA[i];
    }
    __syncthreads();
    if (cg == 0) {
#pragma unroll
        for (int g = 0; g < 3; g++) {
            const float* src = red + (g * 64 + half_id) * 48;
#pragma unroll
            for (int i = 0; i < 16; i++) o0[i] += src[i];
#pragma unroll
            for (int i = 0; i < 8; i++) sA[i] += src[16 + i];
#pragma unroll
            for (int i = 0; i < 24; i++) qA[i] += src[24 + i];
        }

        // ---- epilogue ----
        const float c011 = 0.125f;                 // pw011/sqrt(3)
        const float c101 = 0.17677669529663687f;   // pw101/sqrt(3)
#pragma unroll
        for (int rh = 0; rh < 2; rh++) {
            const int row = rbase + rh * 8;
            float* orow = out + row * 80;
            const int s = rh * 4;
#pragma unroll
            for (int jm = 0; jm < 4; jm++) {
                orow[8 * jm + q2]     = o0[(s + jm) * 2];
                orow[8 * jm + q2 + 1] = o0[(s + jm) * 2 + 1];
            }
            const float x20  = fea_in2[row * 4 + 0];
            const float x21a = fea_in2[row * 4 + 1];
            const float x21b = fea_in2[row * 4 + 2];
            const float x21c = fea_in2[row * 4 + 3];
#pragma unroll
            for (int slot = 0; slot < 4; slot++) {
                const int w = 8 * (slot >> 1) + q2 + (slot & 1);
                const float sv = sA[s + slot];
                orow[32 + 3 * w + 0] = c011 * x21a * sv + c101 * x20 * qA[(s + slot) * 3 + 0];
                orow[32 + 3 * w + 1] = c011 * x21b * sv + c101 * x20 * qA[(s + slot) * 3 + 1];
                orow[32 + 3 * w + 2] = c011 * x21c * sv + c101 * x20 * qA[(s + slot) * 3 + 2];
            }
        }
    }
}

// ---------------------------------------------------------------------------
extern "C" void kernel_launch(void* const* d_in, const int* in_sizes, int n_in,
                              void* d_out, int out_size)
{
    const float* fea_in1    = (const float*)d_in[0];
    const float* fea_in2    = (const float*)d_in[1];
    const float* fea_weight = (const float*)d_in[2];
    const float* W1         = (const float*)d_in[3];
    const float* W2         = (const float*)d_in[4];
    float* out = (float*)d_out;

    cudaFuncSetAttribute(k2_main, cudaFuncAttributeMaxDynamicSharedMemorySize, SMEM_TOTAL);

    k01_prep<<<E_ROWS / 32, 256>>>(fea_in1, fea_in2, fea_weight, W1, W2);
    k2_main<<<E_ROWS / TILE_R, 256, SMEM_TOTAL>>>(fea_in1, fea_in2, out);
}

// round 11
// speedup vs baseline: 1.0591x; 1.0591x over previous
#include <cuda_runtime.h>
#include <cuda_fp16.h>
#include <math.h>
#include <stdint.h>

// ---------------------------------------------------------------------------
// EquiConv v10: fp16 HMMA, B pre-laid-out in GLOBAL memory in mma.sync
//               fragment order -> mainloop has NO smem staging, NO ldmatrix
//               for B, NO __syncthreads. 4 coalesced LDG.128 per ksb feed
//               8 MMAs directly. TILE_R=64, warps=(rg 0..3)x(cg 0..1), occ=2.
//   k01_prep : W2 -> g_B (fragment order)  +  H/silu -> g_H, coefs -> g_C
// ---------------------------------------------------------------------------

#define E_ROWS 65536
#define TILE_R 64
#define NCHUNK 18
#define ASTR   72                   // fp16 elems per A row (64 + 8)
#define SMEM_TOTAL 24576            // A staging (9216) overlaid by reduction

__device__ float g_H[E_ROWS * 64];
__device__ float g_C[E_ROWS * 48];
// fragment-order B: uint4 index = ((chunk*2+cg)*16 + ksb*4 + q)*32 + lane
__device__ __align__(16) __half g_B[NCHUNK * 128 * 64];

// ------------------------------ asm helpers --------------------------------
__device__ __forceinline__ uint32_t smem_u32(const void* p) {
    uint32_t a;
    asm("{ .reg .u64 t; cvta.to.shared.u64 t, %1; cvt.u32.u64 %0, t; }" : "=r"(a) : "l"(p));
    return a;
}
#define LDSM4(r, a)                                                          \
    asm volatile("ldmatrix.sync.aligned.m8n8.x4.shared.b16 {%0,%1,%2,%3},[%4];" \
                 : "=r"((r)[0]), "=r"((r)[1]), "=r"((r)[2]), "=r"((r)[3]) : "r"(a))
#define MMA16816(d, a, b0, b1)                                               \
    asm volatile("mma.sync.aligned.m16n8k16.row.col.f32.f16.f16.f32 "        \
                 "{%0,%1,%2,%3},{%4,%5,%6,%7},{%8,%9},{%0,%1,%2,%3};"        \
                 : "+f"((d)[0]), "+f"((d)[1]), "+f"((d)[2]), "+f"((d)[3])    \
                 : "r"((a)[0]), "r"((a)[1]), "r"((a)[2]), "r"((a)[3]),       \
                   "r"(b0), "r"(b1))

// ---------------------------------------------------------------------------
__global__ void k01_prep(const float* __restrict__ fea_in1,
                         const float* __restrict__ fea_in2,
                         const float* __restrict__ fea_weight,
                         const float* __restrict__ W1,
                         const float* __restrict__ W2)
{
    __shared__ float W1s[64 * 64];
    __shared__ float fws[32 * 64];
    const int t  = threadIdx.x;
    const int r0 = blockIdx.x * 32;

    // ---- k0 part: W2 -> g_B in mma.sync B-fragment order (blocks < 576) ----
    if (blockIdx.x < 576) {
        const int id  = blockIdx.x * 256 + t;   // covers 2304*64 exactly
        const int col = id >> 6, kk = id & 63;
        const int chunk = col >> 7, nn = col & 127;
        const int cgf = (nn >> 6) & 1;
        const int j   = (nn >> 3) & 7;
        const int ns  = nn & 7;
        const int lane = ns * 4 + ((kk & 7) >> 1);
        const int ksb  = kk >> 4;
        const int w    = (kk >> 3) & 1;
        const int q    = j >> 1;
        const int widx = (j & 1) * 2 + w;
        const int elem = kk & 1;
        const int f4   = (((chunk * 2 + cgf) * 16 + ksb * 4 + q) * 32 + lane);
        g_B[f4 * 8 + widx * 2 + elem] = __float2half(W2[kk * 2304 + col]);
    }

    // ---- k1 part ----
    for (int idx = t; idx < 64 * 64; idx += 256) W1s[idx] = W1[idx];
    for (int idx = t; idx < 32 * 64; idx += 256) fws[idx] = fea_weight[r0 * 64 + idx];
    __syncthreads();

    const int rl = t >> 3, l8 = t & 7, grow = r0 + rl;
    float acc[8];
#pragma unroll
    for (int jj = 0; jj < 8; jj++) acc[jj] = 0.f;
#pragma unroll 8
    for (int k = 0; k < 64; k++) {
        const float fv = fws[rl * 64 + k];
#pragma unroll
        for (int jj = 0; jj < 8; jj++) acc[jj] += fv * W1s[k * 64 + jj * 8 + l8];
    }
#pragma unroll
    for (int jj = 0; jj < 8; jj++) {
        const float z = acc[jj] * 0.125f;
        const float s = z / (1.f + expf(-z));
        g_H[grow * 64 + jj * 8 + l8] = 1.679f * s * 0.125f;   // fold W2's /8
    }

    const float x20  = fea_in2[grow * 4 + 0];
    const float x21a = fea_in2[grow * 4 + 1];
    const float x21b = fea_in2[grow * 4 + 2];
    const float x21c = fea_in2[grow * 4 + 3];
    for (int u = l8; u < 32; u += 8)
        g_C[grow * 48 + u] = 0.125f * x20 * fea_in1[grow * 80 + u];      // pw00
    for (int u = l8; u < 16; u += 8) {
        const float* p = fea_in1 + grow * 80 + 32 + u * 3;
        const float b = p[0] * x21a + p[1] * x21b + p[2] * x21c;
        g_C[grow * 48 + 32 + u] = 0.10206207261596575f * b;              // 1/sqrt(96)
    }
}

// ---------------------------------------------------------------------------
// contraction of one chunk's acc (j = 0..7, cols = cg*64 + j*8 + q2 + {0,1})
__device__ __forceinline__ void contract_chunk(
    int m, const float acc[8][4], float* o0, float* sA, float* qA,
    int rbase, int cg, const float* __restrict__ fea_in1)
{
    if (m < 12) {
        const int ubase = (m < 8 ? m * 4 : 32 + (m - 8) * 4) + cg * 2;
#pragma unroll
        for (int rh = 0; rh < 2; rh++) {
            const int row = rbase + rh * 8;
            const float c0v = g_C[row * 48 + ubase];
            const float c1v = g_C[row * 48 + ubase + 1];
#pragma unroll
            for (int j = 0; j < 8; j++) {
                const float c = (j < 4) ? c0v : c1v;
                const int s = (rh * 4 + (j & 3)) * 2;
                o0[s]     = fmaf(c, acc[j][rh * 2],     o0[s]);
                o0[s + 1] = fmaf(c, acc[j][rh * 2 + 1], o0[s + 1]);
            }
        }
    } else if (m < 16) {
        const int u0 = (m - 12) * 8 + cg * 4;
#pragma unroll
        for (int rh = 0; rh < 2; rh++) {
            const int row = rbase + rh * 8;
            const float* xr = fea_in1 + row * 80 + u0;
#pragma unroll
            for (int j = 0; j < 8; j++) {
                const float cu = xr[j >> 1];
                const int s = rh * 4 + (j & 1) * 2;
                sA[s]     = fmaf(cu, acc[j][rh * 2],     sA[s]);
                sA[s + 1] = fmaf(cu, acc[j][rh * 2 + 1], sA[s + 1]);
            }
        }
    } else {
        const int u0 = (m - 16) * 8 + cg * 4;
#pragma unroll
        for (int rh = 0; rh < 2; rh++) {
            const int row = rbase + rh * 8;
            const float* xr = fea_in1 + row * 80 + 32 + 3 * u0;
#pragma unroll
            for (int j = 0; j < 8; j++) {
                const int s = (rh * 4 + (j & 1) * 2) * 3;
#pragma unroll
                for (int k = 0; k < 3; k++) {
                    const float cu = xr[3 * (j >> 1) + k];
                    qA[s + k]     = fmaf(cu, acc[j][rh * 2],     qA[s + k]);
                    qA[s + 3 + k] = fmaf(cu, acc[j][rh * 2 + 1], qA[s + 3 + k]);
                }
            }
        }
    }
}

// ---------------------------------------------------------------------------
__global__ __launch_bounds__(256, 2)
void k2_main(const float* __restrict__ fea_in1,
             const float* __restrict__ fea_in2,
             float* __restrict__ out)
{
    extern __shared__ __align__(16) char smem[];
    const uint32_t sbase = smem_u32(smem);
    const int tid = threadIdx.x, wid = tid >> 5, lane = tid & 31;
    const int rg = wid >> 1, cg = wid & 1;
    const int r0 = blockIdx.x * TILE_R;

    // ---- stage A tile in SMEM just to hoist fragments via ldmatrix ----
    {
        __half* As = (__half*)smem;
        for (int idx = tid; idx < TILE_R * 64; idx += 256) {
            const int r = idx >> 6, j = idx & 63;
            As[r * ASTR + j] = __float2half(g_H[(r0 + r) * 64 + j]);
        }
    }
    __syncthreads();
    const int gp = lane >> 3, lr = lane & 7;
    const uint32_t aBase = sbase + (uint32_t)(((rg * 16 + 8 * (gp & 1) + lr) * ASTR
                                               + 8 * (gp >> 1)) * 2);
    uint32_t afrag[4][4];
#pragma unroll
    for (int ksb = 0; ksb < 4; ksb++)
        LDSM4(afrag[ksb], aBase + ksb * 32);
    __syncthreads();   // A smem reads done; smem reused by reduction later

    // persistent per-thread partial accumulators
    float o0[16], sA[8], qA[24];
#pragma unroll
    for (int i = 0; i < 16; i++) o0[i] = 0.f;
#pragma unroll
    for (int i = 0; i < 8; i++) sA[i] = 0.f;
#pragma unroll
    for (int i = 0; i < 24; i++) qA[i] = 0.f;

    const int rowq = lane >> 2;
    const int rbase = r0 + rg * 16 + rowq;     // + rh*8
    const int q2 = (lane & 3) * 2;

    // B fragment stream: this thread's uint4s for (chunk m, ksb, q):
    //   Bp[m*1024 + ksb*128 + q*32]
    const uint4* Bp = ((const uint4*)g_B) + cg * 512 + lane;

#pragma unroll 1
    for (int m = 0; m < NCHUNK; m++) {
        const uint4* bp = Bp + m * 1024;

        float acc[8][4];
#pragma unroll
        for (int j = 0; j < 8; j++)
#pragma unroll
            for (int c = 0; c < 4; c++) acc[j][c] = 0.f;

#pragma unroll
        for (int ksb = 0; ksb < 4; ksb++) {
            const uint4 b0 = bp[ksb * 128];
            const uint4 b1 = bp[ksb * 128 + 32];
            const uint4 b2 = bp[ksb * 128 + 64];
            const uint4 b3 = bp[ksb * 128 + 96];
            MMA16816(acc[0], afrag[ksb], b0.x, b0.y);
            MMA16816(acc[1], afrag[ksb], b0.z, b0.w);
            MMA16816(acc[2], afrag[ksb], b1.x, b1.y);
            MMA16816(acc[3], afrag[ksb], b1.z, b1.w);
            MMA16816(acc[4], afrag[ksb], b2.x, b2.y);
            MMA16816(acc[5], afrag[ksb], b2.z, b2.w);
            MMA16816(acc[6], afrag[ksb], b3.x, b3.y);
            MMA16816(acc[7], afrag[ksb], b3.z, b3.w);
        }
        contract_chunk(m, acc, o0, sA, qA, rbase, cg, fea_in1);
    }

    // ---- cross-cg reduction (cg=1 partials -> cg=0), reuse smem ----
    __syncthreads();
    float* red = (float*)smem;                 // 128 thr * 48 f = 24576 B
    const int half_id = rg * 32 + lane;
    if (cg == 1) {
        float* dst = red + half_id * 48;
#pragma unroll
        for (int i = 0; i < 16; i++) dst[i] = o0[i];
#pragma unroll
        for (int i = 0; i < 8; i++) dst[16 + i] = sA[i];
#pragma unroll
        for (int i = 0; i < 24; i++) dst[24 + i] = qA[i];
    }
    __syncthreads();
    if (cg == 0) {
        const float* src = red + half_id * 48;
#pragma unroll
        for (int i = 0; i < 16; i++) o0[i] += src[i];
#pragma unroll
        for (int i = 0; i < 8; i++) sA[i] += src[16 + i];
#pragma unroll
        for (int i = 0; i < 24; i++) qA[i] += src[24 + i];

        // ---- epilogue ----
        const float c011 = 0.125f;                 // pw011/sqrt(3)
        const float c101 = 0.17677669529663687f;   // pw101/sqrt(3)
#pragma unroll
        for (int rh = 0; rh < 2; rh++) {
            const int row = rbase + rh * 8;
            float* orow = out + row * 80;
            const int s = rh * 4;
#pragma unroll
            for (int jm = 0; jm < 4; jm++) {
                orow[8 * jm + q2]     = o0[(s + jm) * 2];
                orow[8 * jm + q2 + 1] = o0[(s + jm) * 2 + 1];
            }
            const float x20  = fea_in2[row * 4 + 0];
            const float x21a = fea_in2[row * 4 + 1];
            const float x21b = fea_in2[row * 4 + 2];
            const float x21c = fea_in2[row * 4 + 3];
#pragma unroll
            for (int slot = 0; slot < 4; slot++) {
                const int w = 8 * (slot >> 1) + q2 + (slot & 1);
                const float sv = sA[s + slot];
                orow[32 + 3 * w + 0] = c011 * x21a * sv + c101 * x20 * qA[(s + slot) * 3 + 0];
                orow[32 + 3 * w + 1] = c011 * x21b * sv + c101 * x20 * qA[(s + slot) * 3 + 1];
                orow[32 + 3 * w + 2] = c011 * x21c * sv + c101 * x20 * qA[(s + slot) * 3 + 2];
            }
        }
    }
}

// ---------------------------------------------------------------------------
extern "C" void kernel_launch(void* const* d_in, const int* in_sizes, int n_in,
                              void* d_out, int out_size)
{
    const float* fea_in1    = (const float*)d_in[0];
    const float* fea_in2    = (const float*)d_in[1];
    const float* fea_weight = (const float*)d_in[2];
    const float* W1         = (const float*)d_in[3];
    const float* W2         = (const float*)d_in[4];
    float* out = (float*)d_out;

    cudaFuncSetAttribute(k2_main, cudaFuncAttributeMaxDynamicSharedMemorySize, SMEM_TOTAL);

    k01_prep<<<E_ROWS / 32, 256>>>(fea_in1, fea_in2, fea_weight, W1, W2);
    k2_main<<<E_ROWS / TILE_R, 256, SMEM_TOTAL>>>(fea_in1, fea_in2, out);
}

// round 12
// speedup vs baseline: 1.1696x; 1.1044x over previous
#include <cuda_runtime.h>
#include <cuda_fp16.h>
#include <math.h>
#include <stdint.h>

// ---------------------------------------------------------------------------
// EquiConv v11: R7's tensor-roofline mainloop + fused H/coef prologue.
//   k0_prepB : W2 -> g_B [18 chunks][128 n][64 k] fp16
//   k2_main  : per 64-row CTA: prologue computes H = 1.679*silu((fw@W1)/8)/8
//              straight into the A smem tile (fp16) and seg0/1 coefs into
//              smem Cs — g_H / g_C eliminated. Mainloop: 9 pairs of 128-col
//              chunks, cp.async double-buffered pair buffers, hoisted A
//              fragments, fragment-local contraction, cg-reduction in smem.
// ---------------------------------------------------------------------------

#define E_ROWS 65536
#define TILE_R 64
#define NCHUNK 18
#define NPAIR  9
#define ASTR   72                   // fp16 elems per A row (64 + 8)
#define BSTR   72                   // fp16 elems per B row (64 + 8)
#define A_BYTES (TILE_R*ASTR*2)     // 9216
#define CS_OFF  A_BYTES             // 9216
#define CS_BYTES (TILE_R*48*4)      // 12288
#define BS_OFF  (CS_OFF + CS_BYTES) // 21504
#define BBUF_B  (128*BSTR*2)        // 18432 (one chunk)
#define PAIR_B  (2*BBUF_B)          // 36864 (one pair buffer)
#define SMEM_TOTAL (BS_OFF + 2*PAIR_B)   // 95232

__device__ __align__(16) __half g_B[NCHUNK * 128 * 64];

// ------------------------------ asm helpers --------------------------------
__device__ __forceinline__ uint32_t smem_u32(const void* p) {
    uint32_t a;
    asm("{ .reg .u64 t; cvta.to.shared.u64 t, %1; cvt.u32.u64 %0, t; }" : "=r"(a) : "l"(p));
    return a;
}
#define LDSM4(r, a)                                                          \
    asm volatile("ldmatrix.sync.aligned.m8n8.x4.shared.b16 {%0,%1,%2,%3},[%4];" \
                 : "=r"((r)[0]), "=r"((r)[1]), "=r"((r)[2]), "=r"((r)[3]) : "r"(a))
#define MMA16816(d, a, b0, b1)                                               \
    asm volatile("mma.sync.aligned.m16n8k16.row.col.f32.f16.f16.f32 "        \
                 "{%0,%1,%2,%3},{%4,%5,%6,%7},{%8,%9},{%0,%1,%2,%3};"        \
                 : "+f"((d)[0]), "+f"((d)[1]), "+f"((d)[2]), "+f"((d)[3])    \
                 : "r"((a)[0]), "r"((a)[1]), "r"((a)[2]), "r"((a)[3]),       \
                   "r"(b0), "r"(b1))
#define CP_ASYNC16(d, s) \
    asm volatile("cp.async.cg.shared.global [%0], [%1], 16;" :: "r"(d), "l"(s))
#define CP_COMMIT()   asm volatile("cp.async.commit_group;" ::: "memory")
#define CP_WAIT1()    asm volatile("cp.async.wait_group 1;" ::: "memory")
#define CP_WAIT0()    asm volatile("cp.async.wait_group 0;" ::: "memory")

// stage one pair (2 chunks, 256 rows x 128B) into pair buffer (rows stride 144B)
__device__ __forceinline__ void stage_pair(int pair, uint32_t dst, int tid) {
    const char* src = (const char*)(g_B + pair * 2 * 128 * 64);
#pragma unroll
    for (int it = 0; it < 8; it++) {
        int t16 = tid + it * 256;          // 0..2047
        int row = t16 >> 3, c = t16 & 7;   // row 0..255
        CP_ASYNC16(dst + (uint32_t)(row >> 7) * BBUF_B + (row & 127) * 144 + c * 16,
                   src + row * 128 + c * 16);
    }
}

// ---------------------------------------------------------------------------
__global__ void k0_prepB(const float* __restrict__ W2) {
    int id = blockIdx.x * 256 + threadIdx.x;   // covers 2304*64 exactly
    int col = id >> 6, kk = id & 63;
    int chunk = col >> 7, n = col & 127;
    g_B[(chunk * 128 + n) * 64 + kk] = __float2half(W2[kk * 2304 + col]);
}

// ---------------------------------------------------------------------------
// contraction of one chunk's acc (j = 0..7, cols = cg*64 + j*8 + q2 + {0,1})
__device__ __forceinline__ void contract_chunk(
    int m, const float acc[8][4], float* o0, float* sA, float* qA,
    int rbase, int lrow0, int cg,
    const float* __restrict__ Cs, const float* __restrict__ fea_in1)
{
    if (m < 12) {
        const int ubase = (m < 8 ? m * 4 : 32 + (m - 8) * 4) + cg * 2;
#pragma unroll
        for (int rh = 0; rh < 2; rh++) {
            const int lrow = lrow0 + rh * 8;
            const float c0v = Cs[lrow * 48 + ubase];
            const float c1v = Cs[lrow * 48 + ubase + 1];
#pragma unroll
            for (int j = 0; j < 8; j++) {
                const float c = (j < 4) ? c0v : c1v;
                const int s = (rh * 4 + (j & 3)) * 2;
                o0[s]     = fmaf(c, acc[j][rh * 2],     o0[s]);
                o0[s + 1] = fmaf(c, acc[j][rh * 2 + 1], o0[s + 1]);
            }
        }
    } else if (m < 16) {
        const int u0 = (m - 12) * 8 + cg * 4;
#pragma unroll
        for (int rh = 0; rh < 2; rh++) {
            const int row = rbase + rh * 8;
            const float* xr = fea_in1 + row * 80 + u0;
#pragma unroll
            for (int j = 0; j < 8; j++) {
                const float cu = xr[j >> 1];
                const int s = rh * 4 + (j & 1) * 2;
                sA[s]     = fmaf(cu, acc[j][rh * 2],     sA[s]);
                sA[s + 1] = fmaf(cu, acc[j][rh * 2 + 1], sA[s + 1]);
            }
        }
    } else {
        const int u0 = (m - 16) * 8 + cg * 4;
#pragma unroll
        for (int rh = 0; rh < 2; rh++) {
            const int row = rbase + rh * 8;
            const float* xr = fea_in1 + row * 80 + 32 + 3 * u0;
#pragma unroll
            for (int j = 0; j < 8; j++) {
                const int s = (rh * 4 + (j & 1) * 2) * 3;
#pragma unroll
                for (int k = 0; k < 3; k++) {
                    const float cu = xr[3 * (j >> 1) + k];
                    qA[s + k]     = fmaf(cu, acc[j][rh * 2],     qA[s + k]);
                    qA[s + 3 + k] = fmaf(cu, acc[j][rh * 2 + 1], qA[s + 3 + k]);
                }
            }
        }
    }
}

// ---------------------------------------------------------------------------
__global__ __launch_bounds__(256, 2)
void k2_main(const float* __restrict__ fea_in1,
             const float* __restrict__ fea_in2,
             const float* __restrict__ fea_weight,
             const float* __restrict__ W1,
             float* __restrict__ out)
{
    extern __shared__ __align__(16) char smem[];
    const uint32_t sbase = smem_u32(smem);
    const int tid = threadIdx.x, wid = tid >> 5, lane = tid & 31;
    const int rg = wid >> 1, cg = wid & 1;
    const int r0 = blockIdx.x * TILE_R;

    __half* As = (__half*)smem;
    float*  Cs = (float*)(smem + CS_OFF);

    // ==== fused prologue: H = 1.679*silu((fw@W1)/8)/8 -> As fp16; coefs -> Cs
    {
        float* W1s = (float*)(smem + BS_OFF);            // 16KB transient
        float* fws = (float*)(smem + BS_OFF + 16384);    // 16KB transient
        for (int idx = tid; idx < 64 * 64; idx += 256) W1s[idx] = W1[idx];
        for (int idx = tid; idx < 64 * 64; idx += 256) fws[idx] = fea_weight[r0 * 64 + idx];
        __syncthreads();

        const int rl = tid >> 3, l8 = tid & 7;           // rl 0..31
#pragma unroll 1
        for (int half = 0; half < 2; half++) {
            const int lrow = half * 32 + rl;
            float acc[8];
#pragma unroll
            for (int jj = 0; jj < 8; jj++) acc[jj] = 0.f;
#pragma unroll 8
            for (int k = 0; k < 64; k++) {
                const float fv = fws[lrow * 64 + k];
#pragma unroll
                for (int jj = 0; jj < 8; jj++) acc[jj] += fv * W1s[k * 64 + jj * 8 + l8];
            }
#pragma unroll
            for (int jj = 0; jj < 8; jj++) {
                const float z = acc[jj] * 0.125f;
                const float s = z / (1.f + expf(-z));
                As[lrow * ASTR + jj * 8 + l8] = __float2half(1.679f * s * 0.125f);
            }
            // coefs for this row (8 lanes cooperate per row)
            const int grow = r0 + lrow;
            const float x20  = fea_in2[grow * 4 + 0];
            const float x21a = fea_in2[grow * 4 + 1];
            const float x21b = fea_in2[grow * 4 + 2];
            const float x21c = fea_in2[grow * 4 + 3];
            for (int u = l8; u < 32; u += 8)
                Cs[lrow * 48 + u] = 0.125f * x20 * fea_in1[grow * 80 + u];
            for (int u = l8; u < 16; u += 8) {
                const float* p = fea_in1 + grow * 80 + 32 + u * 3;
                const float b = p[0] * x21a + p[1] * x21b + p[2] * x21c;
                Cs[lrow * 48 + 32 + u] = 0.10206207261596575f * b;
            }
        }
        __syncthreads();   // As/Cs ready; W1s/fws dead -> pair buffers reuse
    }

    // prefetch B pairs 0,1 (overwrites transient W1s/fws area)
    stage_pair(0, sbase + BS_OFF, tid);            CP_COMMIT();
    stage_pair(1, sbase + BS_OFF + PAIR_B, tid);   CP_COMMIT();

    // ldmatrix address groups + hoisted A fragments
    const int gp = lane >> 3, lr = lane & 7;
    const uint32_t aBase = sbase + (uint32_t)(((rg * 16 + 8 * (gp & 1) + lr) * ASTR
                                               + 8 * (gp >> 1)) * 2);
    uint32_t afrag[4][4];
#pragma unroll
    for (int ksb = 0; ksb < 4; ksb++)
        LDSM4(afrag[ksb], aBase + ksb * 32);

    uint32_t bOff[4];
#pragma unroll
    for (int p = 0; p < 4; p++)
        bOff[p] = (uint32_t)(((cg * 64 + 16 * p + 8 * (gp >> 1) + lr) * BSTR
                              + 8 * (gp & 1)) * 2);

    // persistent per-thread partial accumulators
    float o0[16], sA[8], qA[24];
#pragma unroll
    for (int i = 0; i < 16; i++) o0[i] = 0.f;
#pragma unroll
    for (int i = 0; i < 8; i++) sA[i] = 0.f;
#pragma unroll
    for (int i = 0; i < 24; i++) qA[i] = 0.f;

    const int rowq = lane >> 2;
    const int lrow0 = rg * 16 + rowq;          // local row (+ rh*8)
    const int rbase = r0 + lrow0;
    const int q2 = (lane & 3) * 2;

    float acc[8][4];

#pragma unroll 1
    for (int p = 0; p < NPAIR; p++) {
        if (p < NPAIR - 1) { CP_WAIT1(); } else { CP_WAIT0(); }
        __syncthreads();
        const uint32_t pbuf = sbase + BS_OFF + (uint32_t)(p & 1) * PAIR_B;

        // chunk 2p
#pragma unroll
        for (int j = 0; j < 8; j++)
#pragma unroll
            for (int c = 0; c < 4; c++) acc[j][c] = 0.f;
#pragma unroll
        for (int ksb = 0; ksb < 4; ksb++) {
#pragma unroll
            for (int pp = 0; pp < 4; pp++) {
                uint32_t r[4];
                LDSM4(r, pbuf + bOff[pp] + ksb * 32);
                MMA16816(acc[2 * pp],     afrag[ksb], r[0], r[1]);
                MMA16816(acc[2 * pp + 1], afrag[ksb], r[2], r[3]);
            }
        }
        contract_chunk(2 * p, acc, o0, sA, qA, rbase, lrow0, cg, Cs, fea_in1);

        // chunk 2p+1
#pragma unroll
        for (int j = 0; j < 8; j++)
#pragma unroll
            for (int c = 0; c < 4; c++) acc[j][c] = 0.f;
#pragma unroll
        for (int ksb = 0; ksb < 4; ksb++) {
#pragma unroll
            for (int pp = 0; pp < 4; pp++) {
                uint32_t r[4];
                LDSM4(r, pbuf + BBUF_B + bOff[pp] + ksb * 32);
                MMA16816(acc[2 * pp],     afrag[ksb], r[0], r[1]);
                MMA16816(acc[2 * pp + 1], afrag[ksb], r[2], r[3]);
            }
        }
        __syncthreads();                      // all B reads of this pair done
        if (p + 2 < NPAIR) {                  // refill this pair buffer
            stage_pair(p + 2, pbuf, tid);
            CP_COMMIT();
        }
        contract_chunk(2 * p + 1, acc, o0, sA, qA, rbase, lrow0, cg, Cs, fea_in1);
    }

    // ---- cross-cg reduction (cg=1 partials -> cg=0), reuse B area ----
    float* red = (float*)(smem + BS_OFF);      // 128 thr * 48 f = 24576 B
    const int half_id = rg * 32 + lane;
    if (cg == 1) {
        float* dst = red + half_id * 48;
#pragma unroll
        for (int i = 0; i < 16; i++) dst[i] = o0[i];
#pragma unroll
        for (int i = 0; i < 8; i++) dst[16 + i] = sA[i];
#pragma unroll
        for (int i = 0; i < 24; i++) dst[24 + i] = qA[i];
    }
    __syncthreads();
    if (cg == 0) {
        const float* src = red + half_id * 48;
#pragma unroll
        for (int i = 0; i < 16; i++) o0[i] += src[i];
#pragma unroll
        for (int i = 0; i < 8; i++) sA[i] += src[16 + i];
#pragma unroll
        for (int i = 0; i < 24; i++) qA[i] += src[24 + i];

        // ---- epilogue ----
        const float c011 = 0.125f;                 // pw011/sqrt(3)
        const float c101 = 0.17677669529663687f;   // pw101/sqrt(3)
#pragma unroll
        for (int rh = 0; rh < 2; rh++) {
            const int row = rbase + rh * 8;
            float* orow = out + row * 80;
            const int s = rh * 4;
#pragma unroll
            for (int jm = 0; jm < 4; jm++) {
                orow[8 * jm + q2]     = o0[(s + jm) * 2];
                orow[8 * jm + q2 + 1] = o0[(s + jm) * 2 + 1];
            }
            const float x20  = fea_in2[row * 4 + 0];
            const float x21a = fea_in2[row * 4 + 1];
            const float x21b = fea_in2[row * 4 + 2];
            const float x21c = fea_in2[row * 4 + 3];
#pragma unroll
            for (int slot = 0; slot < 4; slot++) {
                const int w = 8 * (slot >> 1) + q2 + (slot & 1);
                const float sv = sA[s + slot];
                orow[32 + 3 * w + 0] = c011 * x21a * sv + c101 * x20 * qA[(s + slot) * 3 + 0];
                orow[32 + 3 * w + 1] = c011 * x21b * sv + c101 * x20 * qA[(s + slot) * 3 + 1];
                orow[32 + 3 * w + 2] = c011 * x21c * sv + c101 * x20 * qA[(s + slot) * 3 + 2];
            }
        }
    }
}

// ---------------------------------------------------------------------------
extern "C" void kernel_launch(void* const* d_in, const int* in_sizes, int n_in,
                              void* d_out, int out_size)
{
    const float* fea_in1    = (const float*)d_in[0];
    const float* fea_in2    = (const float*)d_in[1];
    const float* fea_weight = (const float*)d_in[2];
    const float* W1         = (const float*)d_in[3];
    const float* W2         = (const float*)d_in[4];
    float* out = (float*)d_out;

    cudaFuncSetAttribute(k2_main, cudaFuncAttributeMaxDynamicSharedMemorySize, SMEM_TOTAL);

    k0_prepB<<<576, 256>>>(W2);
    k2_main<<<E_ROWS / TILE_R, 256, SMEM_TOTAL>>>(fea_in1, fea_in2, fea_weight, W1, out);
}